// round 1
// baseline (speedup 1.0000x reference)
#include <cuda_runtime.h>

// Problem shape (fixed by reference):
//   x  : [B=4, S=2048, D=1024] fp32
//   Wq/Wk/Wv : [D, D] fp32   (y = x @ W^T)
//   out: [B, S, D] fp32
#define BATCH 4
#define SEQ   2048
#define DM    1024
#define MTOT  (BATCH * SEQ)   // 8192

// Scratch (static __device__ arrays: allocation-free, harness-legal)
__device__ float g_Q[BATCH * SEQ * DM];     // 32 MB
__device__ float g_K[BATCH * SEQ * DM];     // 32 MB
__device__ float g_V[BATCH * SEQ * DM];     // 32 MB
__device__ float g_P[BATCH * SEQ * SEQ];    // 64 MB (scores / probs)

// ---------------------------------------------------------------------------
// Tiled SGEMM cores. 128x128 tile, BK=8, 256 threads, 8x8 register micro-tile.
// Two variants:
//   abt: C[m][n] = sum_k A[m][k] * B[n][k]   (A row-major [M,K], B row-major [N,K])
//   ab : C[m][n] = sum_k A[m][k] * B[k][n]   (A row-major [M,K], B row-major [K,N])
// All dims here are multiples of the tile sizes -> no bounds checks.
// ---------------------------------------------------------------------------
#define BM 128
#define BN 128
#define BK 8
#define TM 8
#define TN 8

__device__ __forceinline__ void sgemm_abt_body(
    const float* __restrict__ A, const float* __restrict__ Bm,
    float* __restrict__ C, int N, int K)
{
    __shared__ float As[BK][BM];
    __shared__ float Bs[BK][BN];

    const int t  = threadIdx.x;            // 0..255
    const int m0 = blockIdx.y * BM;
    const int n0 = blockIdx.x * BN;

    // Tile loader mapping: 128 rows x 8 k-cols, one float4 per thread.
    const int lr = t >> 1;                 // 0..127
    const int lc = (t & 1) * 4;            // 0 or 4

    const int ty = t >> 4;                 // 0..15
    const int tx = t & 15;                 // 0..15

    float acc[TM][TN];
#pragma unroll
    for (int i = 0; i < TM; i++)
#pragma unroll
        for (int j = 0; j < TN; j++) acc[i][j] = 0.f;

    for (int k0 = 0; k0 < K; k0 += BK) {
        float4 a4 = *(const float4*)(A  + (long)(m0 + lr) * K + k0 + lc);
        float4 b4 = *(const float4*)(Bm + (long)(n0 + lr) * K + k0 + lc);
        As[lc + 0][lr] = a4.x; As[lc + 1][lr] = a4.y;
        As[lc + 2][lr] = a4.z; As[lc + 3][lr] = a4.w;
        Bs[lc + 0][lr] = b4.x; Bs[lc + 1][lr] = b4.y;
        Bs[lc + 2][lr] = b4.z; Bs[lc + 3][lr] = b4.w;
        __syncthreads();

#pragma unroll
        for (int k = 0; k < BK; k++) {
            float a[TM], b[TN];
            float4 a0 = *(const float4*)&As[k][ty * TM];
            float4 a1 = *(const float4*)&As[k][ty * TM + 4];
            float4 b0 = *(const float4*)&Bs[k][tx * TN];
            float4 b1 = *(const float4*)&Bs[k][tx * TN + 4];
            a[0]=a0.x; a[1]=a0.y; a[2]=a0.z; a[3]=a0.w;
            a[4]=a1.x; a[5]=a1.y; a[6]=a1.z; a[7]=a1.w;
            b[0]=b0.x; b[1]=b0.y; b[2]=b0.z; b[3]=b0.w;
            b[4]=b1.x; b[5]=b1.y; b[6]=b1.z; b[7]=b1.w;
#pragma unroll
            for (int i = 0; i < TM; i++)
#pragma unroll
                for (int j = 0; j < TN; j++)
                    acc[i][j] = fmaf(a[i], b[j], acc[i][j]);
        }
        __syncthreads();
    }

#pragma unroll
    for (int i = 0; i < TM; i++) {
        float4* p = (float4*)(C + (long)(m0 + ty * TM + i) * N + n0 + tx * TN);
        p[0] = make_float4(acc[i][0], acc[i][1], acc[i][2], acc[i][3]);
        p[1] = make_float4(acc[i][4], acc[i][5], acc[i][6], acc[i][7]);
    }
}

__device__ __forceinline__ void sgemm_ab_body(
    const float* __restrict__ A, const float* __restrict__ Bm,
    float* __restrict__ C, int N, int K)
{
    __shared__ float As[BK][BM];
    __shared__ float Bs[BK][BN];

    const int t  = threadIdx.x;
    const int m0 = blockIdx.y * BM;
    const int n0 = blockIdx.x * BN;

    const int lrA = t >> 1;
    const int lcA = (t & 1) * 4;
    const int lrB = t >> 5;                // 0..7
    const int lcB = (t & 31) * 4;          // 0..124

    const int ty = t >> 4;
    const int tx = t & 15;

    float acc[TM][TN];
#pragma unroll
    for (int i = 0; i < TM; i++)
#pragma unroll
        for (int j = 0; j < TN; j++) acc[i][j] = 0.f;

    for (int k0 = 0; k0 < K; k0 += BK) {
        float4 a4 = *(const float4*)(A + (long)(m0 + lrA) * K + k0 + lcA);
        As[lcA + 0][lrA] = a4.x; As[lcA + 1][lrA] = a4.y;
        As[lcA + 2][lrA] = a4.z; As[lcA + 3][lrA] = a4.w;
        // B is [K, N] row-major: load 8 rows x 128 cols, coalesced along n.
        float4 b4 = *(const float4*)(Bm + (long)(k0 + lrB) * N + n0 + lcB);
        *(float4*)&Bs[lrB][lcB] = b4;
        __syncthreads();

#pragma unroll
        for (int k = 0; k < BK; k++) {
            float a[TM], b[TN];
            float4 a0 = *(const float4*)&As[k][ty * TM];
            float4 a1 = *(const float4*)&As[k][ty * TM + 4];
            float4 b0 = *(const float4*)&Bs[k][tx * TN];
            float4 b1 = *(const float4*)&Bs[k][tx * TN + 4];
            a[0]=a0.x; a[1]=a0.y; a[2]=a0.z; a[3]=a0.w;
            a[4]=a1.x; a[5]=a1.y; a[6]=a1.z; a[7]=a1.w;
            b[0]=b0.x; b[1]=b0.y; b[2]=b0.z; b[3]=b0.w;
            b[4]=b1.x; b[5]=b1.y; b[6]=b1.z; b[7]=b1.w;
#pragma unroll
            for (int i = 0; i < TM; i++)
#pragma unroll
                for (int j = 0; j < TN; j++)
                    acc[i][j] = fmaf(a[i], b[j], acc[i][j]);
        }
        __syncthreads();
    }

#pragma unroll
    for (int i = 0; i < TM; i++) {
        float4* p = (float4*)(C + (long)(m0 + ty * TM + i) * N + n0 + tx * TN);
        p[0] = make_float4(acc[i][0], acc[i][1], acc[i][2], acc[i][3]);
        p[1] = make_float4(acc[i][4], acc[i][5], acc[i][6], acc[i][7]);
    }
}

// ---------------------------------------------------------------------------
// Stage kernels
// ---------------------------------------------------------------------------

// Q/K/V = x @ W^T  (M=8192, N=1024, K=1024), grid.z selects the weight.
__global__ __launch_bounds__(256) void qkv_kernel(
    const float* __restrict__ x,
    const float* __restrict__ Wq,
    const float* __restrict__ Wk,
    const float* __restrict__ Wv)
{
    const float* W = (blockIdx.z == 0) ? Wq : (blockIdx.z == 1) ? Wk : Wv;
    float* C       = (blockIdx.z == 0) ? g_Q : (blockIdx.z == 1) ? g_K : g_V;
    sgemm_abt_body(x, W, C, DM, DM);
}

// scores[b] = Q[b] @ K[b]^T  (M=N=2048, K=1024), grid.z = batch.
__global__ __launch_bounds__(256) void scores_kernel()
{
    const long b = blockIdx.z;
    sgemm_abt_body(g_Q + b * (long)SEQ * DM,
                   g_K + b * (long)SEQ * DM,
                   g_P + b * (long)SEQ * SEQ, SEQ, DM);
}

// Row softmax over g_P with 1/sqrt(D) scaling. One block (256 thr) per row.
__global__ __launch_bounds__(256) void softmax_kernel()
{
    const long row = blockIdx.x;              // 0 .. BATCH*SEQ-1
    float* p = g_P + row * (long)SEQ;
    const int t = threadIdx.x;
    const float scale = 0.03125f;             // 1/sqrt(1024)

    float4 v0 = ((const float4*)p)[t];
    float4 v1 = ((const float4*)p)[t + 256];

    float m = fmaxf(fmaxf(fmaxf(v0.x, v0.y), fmaxf(v0.z, v0.w)),
                    fmaxf(fmaxf(v1.x, v1.y), fmaxf(v1.z, v1.w)));
    m *= scale;

    __shared__ float red[256];
    red[t] = m; __syncthreads();
#pragma unroll
    for (int s = 128; s > 0; s >>= 1) {
        if (t < s) red[t] = fmaxf(red[t], red[t + s]);
        __syncthreads();
    }
    const float rowmax = red[0];
    __syncthreads();

    float e[8];
    e[0] = __expf(fmaf(v0.x, scale, -rowmax));
    e[1] = __expf(fmaf(v0.y, scale, -rowmax));
    e[2] = __expf(fmaf(v0.z, scale, -rowmax));
    e[3] = __expf(fmaf(v0.w, scale, -rowmax));
    e[4] = __expf(fmaf(v1.x, scale, -rowmax));
    e[5] = __expf(fmaf(v1.y, scale, -rowmax));
    e[6] = __expf(fmaf(v1.z, scale, -rowmax));
    e[7] = __expf(fmaf(v1.w, scale, -rowmax));

    float s8 = e[0] + e[1] + e[2] + e[3] + e[4] + e[5] + e[6] + e[7];
    red[t] = s8; __syncthreads();
#pragma unroll
    for (int s = 128; s > 0; s >>= 1) {
        if (t < s) red[t] += red[t + s];
        __syncthreads();
    }
    const float inv = 1.0f / red[0];

    ((float4*)p)[t]       = make_float4(e[0] * inv, e[1] * inv, e[2] * inv, e[3] * inv);
    ((float4*)p)[t + 256] = make_float4(e[4] * inv, e[5] * inv, e[6] * inv, e[7] * inv);
}

// out[b] = P[b] @ V[b]  (M=2048, N=1024, K=2048), grid.z = batch.
__global__ __launch_bounds__(256) void out_kernel(float* __restrict__ out)
{
    const long b = blockIdx.z;
    sgemm_ab_body(g_P + b * (long)SEQ * SEQ,
                  g_V + b * (long)SEQ * DM,
                  out + b * (long)SEQ * DM, DM, SEQ);
}

// ---------------------------------------------------------------------------
extern "C" void kernel_launch(void* const* d_in, const int* in_sizes, int n_in,
                              void* d_out, int out_size)
{
    const float* x  = (const float*)d_in[0];
    const float* Wq = (const float*)d_in[1];
    const float* Wk = (const float*)d_in[2];
    const float* Wv = (const float*)d_in[3];
    float* out = (float*)d_out;

    dim3 blk(256);
    qkv_kernel   <<<dim3(DM / BN,  MTOT / BM, 3),     blk>>>(x, Wq, Wk, Wv);
    scores_kernel<<<dim3(SEQ / BN, SEQ / BM,  BATCH), blk>>>();
    softmax_kernel<<<BATCH * SEQ, 256>>>();
    out_kernel   <<<dim3(DM / BN,  SEQ / BM,  BATCH), blk>>>(out);
}

// round 2
// speedup vs baseline: 2.6106x; 2.6106x over previous
#include <cuda_runtime.h>
#include <cstdint>

// Shape: x [B=4, S=2048, D=1024] fp32; Wq/Wk/Wv [D, D] fp32 (y = x @ W^T)
#define BATCH 4
#define SEQ   2048
#define DM    1024
#define MTOT  (BATCH * SEQ)   // 8192

// Scratch
__device__ float g_Q[BATCH * SEQ * DM];
__device__ float g_K[BATCH * SEQ * DM];
__device__ float g_V[BATCH * SEQ * DM];
__device__ float g_P[BATCH * SEQ * SEQ];

// ---------------------------------------------------------------------------
// TF32 mma.sync GEMM core.
// Block tile 128x128, BK=16, 256 threads = 8 warps in a 2x4 grid.
// Warp tile 64x32 = 4x4 grid of m16n8k8 HMMAs, 2 k-steps per k-tile.
// smem stride 136 floats (8 mod 32) -> conflict-free fragment loads.
// ---------------------------------------------------------------------------
#define BM 128
#define BN 128
#define BK 16
#define SSTR 136   // smem row stride in 4B words

__device__ __forceinline__ uint32_t f2tf32(float f) {
    uint32_t o;
    asm("cvt.rna.tf32.f32 %0, %1;" : "=r"(o) : "f"(f));
    return o;
}

__device__ __forceinline__ void mma_tf32(
    float c[4], uint32_t a0, uint32_t a1, uint32_t a2, uint32_t a3,
    uint32_t b0, uint32_t b1)
{
    asm volatile(
        "mma.sync.aligned.m16n8k8.row.col.f32.tf32.tf32.f32 "
        "{%0,%1,%2,%3}, {%4,%5,%6,%7}, {%8,%9}, {%0,%1,%2,%3};"
        : "+f"(c[0]), "+f"(c[1]), "+f"(c[2]), "+f"(c[3])
        : "r"(a0), "r"(a1), "r"(a2), "r"(a3), "r"(b0), "r"(b1));
}

// B_NK = true : C[m][n] = sum_k A[m][k] * B[n][k]   (B row-major [N,K])
// B_NK = false: C[m][n] = sum_k A[m][k] * B[k][n]   (B row-major [K,N])
template <bool B_NK>
__device__ __forceinline__ void gemm_tf32_body(
    const float* __restrict__ A, const float* __restrict__ Bm,
    float* __restrict__ C, int N, int K)
{
    __shared__ uint32_t As[BK][SSTR];
    __shared__ uint32_t Bs[BK][SSTR];

    const int t    = threadIdx.x;
    const int lane = t & 31;
    const int warp = t >> 5;
    const int m0   = blockIdx.y * BM;
    const int n0   = blockIdx.x * BN;

    const int wm = (warp >> 2) * 64;   // warp row offset in tile
    const int wn = (warp & 3) * 32;    // warp col offset in tile
    const int fr = lane >> 2;          // fragment row (groupID)
    const int fc = lane & 3;           // fragment col (tid-in-group)

    float acc[4][4][4];
#pragma unroll
    for (int i = 0; i < 4; i++)
#pragma unroll
        for (int j = 0; j < 4; j++)
#pragma unroll
            for (int r = 0; r < 4; r++) acc[i][j][r] = 0.f;

    // Loader mapping (512 float4 per tile per array, 2 per thread)
    // A (and B_NK): idx -> row = idx>>2 (0..127), kq = (idx&3)*4
    // B (K,N)     : idx -> k = idx>>5 (0..15),  n4 = (idx&31)*4
    const int a_row0 = t >> 1;               // unused alt mapping placeholder
    (void)a_row0;

    float4 pa[2], pb[2];
    // prefetch tile 0
#pragma unroll
    for (int it = 0; it < 2; it++) {
        int idx = t + it * 256;
        int row = idx >> 2, kq = (idx & 3) * 4;
        pa[it] = *(const float4*)(A + (long)(m0 + row) * K + kq);
        if (B_NK) {
            pb[it] = *(const float4*)(Bm + (long)(n0 + row) * K + kq);
        } else {
            int k = idx >> 5, n4 = (idx & 31) * 4;
            pb[it] = *(const float4*)(Bm + (long)k * N + n0 + n4);
        }
    }

    for (int k0 = 0; k0 < K; k0 += BK) {
        // store prefetched tile to smem (with tf32 rounding)
#pragma unroll
        for (int it = 0; it < 2; it++) {
            int idx = t + it * 256;
            int row = idx >> 2, kq = (idx & 3) * 4;
            As[kq + 0][row] = f2tf32(pa[it].x);
            As[kq + 1][row] = f2tf32(pa[it].y);
            As[kq + 2][row] = f2tf32(pa[it].z);
            As[kq + 3][row] = f2tf32(pa[it].w);
            if (B_NK) {
                Bs[kq + 0][row] = f2tf32(pb[it].x);
                Bs[kq + 1][row] = f2tf32(pb[it].y);
                Bs[kq + 2][row] = f2tf32(pb[it].z);
                Bs[kq + 3][row] = f2tf32(pb[it].w);
            } else {
                int k = idx >> 5, n4 = (idx & 31) * 4;
                Bs[k][n4 + 0] = f2tf32(pb[it].x);
                Bs[k][n4 + 1] = f2tf32(pb[it].y);
                Bs[k][n4 + 2] = f2tf32(pb[it].z);
                Bs[k][n4 + 3] = f2tf32(pb[it].w);
            }
        }
        __syncthreads();

        // prefetch next tile
        if (k0 + BK < K) {
            int kn = k0 + BK;
#pragma unroll
            for (int it = 0; it < 2; it++) {
                int idx = t + it * 256;
                int row = idx >> 2, kq = (idx & 3) * 4;
                pa[it] = *(const float4*)(A + (long)(m0 + row) * K + kn + kq);
                if (B_NK) {
                    pb[it] = *(const float4*)(Bm + (long)(n0 + row) * K + kn + kq);
                } else {
                    int k = idx >> 5, n4 = (idx & 31) * 4;
                    pb[it] = *(const float4*)(Bm + (long)(kn + k) * N + n0 + n4);
                }
            }
        }

        // compute: 2 k-steps of 8
#pragma unroll
        for (int ks = 0; ks < 2; ks++) {
            const int kb = ks * 8;
            uint32_t af[4][4], bf[4][2];
#pragma unroll
            for (int im = 0; im < 4; im++) {
                int m = wm + im * 16 + fr;
                af[im][0] = As[kb + fc    ][m];
                af[im][1] = As[kb + fc    ][m + 8];
                af[im][2] = As[kb + fc + 4][m];
                af[im][3] = As[kb + fc + 4][m + 8];
            }
#pragma unroll
            for (int in = 0; in < 4; in++) {
                int n = wn + in * 8 + fr;
                bf[in][0] = Bs[kb + fc    ][n];
                bf[in][1] = Bs[kb + fc + 4][n];
            }
#pragma unroll
            for (int im = 0; im < 4; im++)
#pragma unroll
                for (int in = 0; in < 4; in++)
                    mma_tf32(acc[im][in], af[im][0], af[im][1], af[im][2], af[im][3],
                             bf[in][0], bf[in][1]);
        }
        __syncthreads();
    }

    // epilogue: c0/c1 at (fr, 2fc), c2/c3 at (fr+8, 2fc)
#pragma unroll
    for (int im = 0; im < 4; im++) {
#pragma unroll
        for (int in = 0; in < 4; in++) {
            long row = m0 + wm + im * 16 + fr;
            long col = n0 + wn + in * 8 + 2 * fc;
            *(float2*)(C + row * N + col)       = make_float2(acc[im][in][0], acc[im][in][1]);
            *(float2*)(C + (row + 8) * N + col) = make_float2(acc[im][in][2], acc[im][in][3]);
        }
    }
}

// ---------------------------------------------------------------------------
// Stage kernels
// ---------------------------------------------------------------------------
__global__ __launch_bounds__(256) void qkv_kernel(
    const float* __restrict__ x,
    const float* __restrict__ Wq,
    const float* __restrict__ Wk,
    const float* __restrict__ Wv)
{
    const float* W = (blockIdx.z == 0) ? Wq : (blockIdx.z == 1) ? Wk : Wv;
    float* C       = (blockIdx.z == 0) ? g_Q : (blockIdx.z == 1) ? g_K : g_V;
    gemm_tf32_body<true>(x, W, C, DM, DM);
}

__global__ __launch_bounds__(256) void scores_kernel()
{
    const long b = blockIdx.z;
    gemm_tf32_body<true>(g_Q + b * (long)SEQ * DM,
                         g_K + b * (long)SEQ * DM,
                         g_P + b * (long)SEQ * SEQ, SEQ, DM);
}

__global__ __launch_bounds__(256) void softmax_kernel()
{
    const long row = blockIdx.x;
    float* p = g_P + row * (long)SEQ;
    const int t = threadIdx.x;
    const float scale = 0.03125f;  // 1/sqrt(1024)

    float4 v0 = ((const float4*)p)[t];
    float4 v1 = ((const float4*)p)[t + 256];

    float m = fmaxf(fmaxf(fmaxf(v0.x, v0.y), fmaxf(v0.z, v0.w)),
                    fmaxf(fmaxf(v1.x, v1.y), fmaxf(v1.z, v1.w)));
    m *= scale;

    __shared__ float red[256];
    red[t] = m; __syncthreads();
#pragma unroll
    for (int s = 128; s > 0; s >>= 1) {
        if (t < s) red[t] = fmaxf(red[t], red[t + s]);
        __syncthreads();
    }
    const float rowmax = red[0];
    __syncthreads();

    float e[8];
    e[0] = __expf(fmaf(v0.x, scale, -rowmax));
    e[1] = __expf(fmaf(v0.y, scale, -rowmax));
    e[2] = __expf(fmaf(v0.z, scale, -rowmax));
    e[3] = __expf(fmaf(v0.w, scale, -rowmax));
    e[4] = __expf(fmaf(v1.x, scale, -rowmax));
    e[5] = __expf(fmaf(v1.y, scale, -rowmax));
    e[6] = __expf(fmaf(v1.z, scale, -rowmax));
    e[7] = __expf(fmaf(v1.w, scale, -rowmax));

    float s8 = e[0]+e[1]+e[2]+e[3]+e[4]+e[5]+e[6]+e[7];
    red[t] = s8; __syncthreads();
#pragma unroll
    for (int s = 128; s > 0; s >>= 1) {
        if (t < s) red[t] += red[t + s];
        __syncthreads();
    }
    const float inv = 1.0f / red[0];

    ((float4*)p)[t]       = make_float4(e[0]*inv, e[1]*inv, e[2]*inv, e[3]*inv);
    ((float4*)p)[t + 256] = make_float4(e[4]*inv, e[5]*inv, e[6]*inv, e[7]*inv);
}

__global__ __launch_bounds__(256) void out_kernel(float* __restrict__ out)
{
    const long b = blockIdx.z;
    gemm_tf32_body<false>(g_P + b * (long)SEQ * SEQ,
                          g_V + b * (long)SEQ * DM,
                          out + b * (long)SEQ * DM, DM, SEQ);
}

// ---------------------------------------------------------------------------
extern "C" void kernel_launch(void* const* d_in, const int* in_sizes, int n_in,
                              void* d_out, int out_size)
{
    const float* x  = (const float*)d_in[0];
    const float* Wq = (const float*)d_in[1];
    const float* Wk = (const float*)d_in[2];
    const float* Wv = (const float*)d_in[3];
    float* out = (float*)d_out;

    dim3 blk(256);
    qkv_kernel   <<<dim3(DM / BN,  MTOT / BM, 3),     blk>>>(x, Wq, Wk, Wv);
    scores_kernel<<<dim3(SEQ / BN, SEQ / BM,  BATCH), blk>>>();
    softmax_kernel<<<BATCH * SEQ, 256>>>();
    out_kernel   <<<dim3(DM / BN,  SEQ / BM,  BATCH), blk>>>(out);
}